// round 16
// baseline (speedup 1.0000x reference)
#include <cuda_runtime.h>
#include <cstdint>

// Householder reflection per row, B=8192, L=4096, fp32.
//   out[b,:] = z[b,:] - 2 * v[b,:] * (v.z)/(v.v)
//
// R16: hybrid request paths. v streams via cp.async.bulk (TMA engine) into
// 16KB smem; z streams via per-thread __ldcs LDG (LSU path) directly into
// registers. The two read streams ride different front-end queues
// concurrently; each path carries half the load (halved L1tex queue depth
// vs R1, halved TMA stream count vs R7). z stays register-resident for both
// dot and output; v is read twice from smem (DRAM-neutral per R9).

constexpr int THREADS = 256;
constexpr int L       = 4096;
constexpr int L4      = L / 4;             // 1024 float4 per row
constexpr int PER     = L4 / THREADS;      // 4 float4 per thread per tensor
constexpr int ROW_BYTES = L * 4;           // 16384 (v only in smem)

__device__ __forceinline__ uint32_t smem_u32(const void* p) {
    return (uint32_t)__cvta_generic_to_shared(p);
}

__global__ __launch_bounds__(THREADS)
void hh_hybrid_r16_kernel(const float4* __restrict__ v,
                          const float4* __restrict__ z,
                          float4* __restrict__ out)
{
    extern __shared__ float4 sm[];            // v: [0,1024)
    __shared__ __align__(8) unsigned long long mbar;
    __shared__ float s_part[16];              // 8 warps x {vz, vv}
    __shared__ float s_scale;

    const int t    = threadIdx.x;
    const int lane = t & 31;
    const int wid  = t >> 5;
    const size_t base = (size_t)blockIdx.x * L4;

    const uint32_t mb = smem_u32(&mbar);

    if (t == 0) {
        asm volatile("mbarrier.init.shared::cta.b64 [%0], %1;"
                     :: "r"(mb), "r"(1));
        asm volatile("fence.proxy.async.shared::cta;" ::: "memory");
    }
    __syncthreads();

    // TMA path: v -> smem
    if (t == 0) {
        asm volatile("mbarrier.arrive.expect_tx.shared::cta.b64 _, [%0], %1;"
                     :: "r"(mb), "r"(ROW_BYTES) : "memory");
        asm volatile("cp.async.bulk.shared::cta.global.mbarrier::complete_tx::bytes"
                     " [%0], [%1], %2, [%3];"
                     :: "r"(smem_u32(sm)), "l"(v + base), "r"(ROW_BYTES), "r"(mb)
                     : "memory");
    }

    // LSU path: z -> registers (front-batched, streams concurrently with TMA)
    const float4* zg = z + base;
    float4 rz[PER];
    #pragma unroll
    for (int i = 0; i < PER; i++)
        rz[i] = __ldcs(zg + t + i * THREADS);

    // Wait for v (parity 0, single-shot), acquire for generic smem reads
    {
        uint32_t done;
        asm volatile(
            "{\n\t.reg .pred p;\n\t"
            "mbarrier.try_wait.parity.acquire.cta.shared::cta.b64 p, [%1], %2;\n\t"
            "selp.b32 %0, 1, 0, p;\n\t}"
            : "=r"(done) : "r"(mb), "r"(0) : "memory");
        while (!done) {
            asm volatile(
                "{\n\t.reg .pred p;\n\t"
                "mbarrier.try_wait.parity.acquire.cta.shared::cta.b64 p, [%1], %2, 0x989680;\n\t"
                "selp.b32 %0, 1, 0, p;\n\t}"
                : "=r"(done) : "r"(mb), "r"(0) : "memory");
        }
    }

    // Dot pass: v from smem, z from registers
    float dvz = 0.0f, dvv = 0.0f;
    #pragma unroll
    for (int i = 0; i < PER; i++) {
        const float4 a = sm[t + i * THREADS];
        dvz += a.x * rz[i].x + a.y * rz[i].y + a.z * rz[i].z + a.w * rz[i].w;
        dvv += a.x * a.x + a.y * a.y + a.z * a.z + a.w * a.w;
    }

    #pragma unroll
    for (int off = 16; off > 0; off >>= 1) {
        dvz += __shfl_xor_sync(0xFFFFFFFFu, dvz, off);
        dvv += __shfl_xor_sync(0xFFFFFFFFu, dvv, off);
    }
    if (lane == 0) { s_part[wid] = dvz; s_part[8 + wid] = dvv; }
    __syncthreads();

    if (wid == 0) {
        float a = (lane < 8) ? s_part[lane] : 0.0f;
        float c = (lane < 8) ? s_part[8 + lane] : 0.0f;
        #pragma unroll
        for (int off = 4; off > 0; off >>= 1) {
            a += __shfl_xor_sync(0xFFFFFFFFu, a, off);
            c += __shfl_xor_sync(0xFFFFFFFFu, c, off);
        }
        if (lane == 0) s_scale = 2.0f * a / c;
    }
    __syncthreads();

    const float nscale = -s_scale;
    float4* og = out + base;

    // Output: v re-read from smem, z from registers, streaming stores
    #pragma unroll
    for (int i = 0; i < PER; i++) {
        const float4 a = sm[t + i * THREADS];
        float4 o;
        o.x = fmaf(nscale, a.x, rz[i].x);
        o.y = fmaf(nscale, a.y, rz[i].y);
        o.z = fmaf(nscale, a.z, rz[i].z);
        o.w = fmaf(nscale, a.w, rz[i].w);
        __stcs(og + t + i * THREADS, o);
    }
}

extern "C" void kernel_launch(void* const* d_in, const int* in_sizes, int n_in,
                              void* d_out, int out_size)
{
    const float4* v = (const float4*)d_in[0];
    const float4* z = (const float4*)d_in[1];
    float4* out = (float4*)d_out;

    const int B = in_sizes[0] / L;    // 8192

    static bool attr_set = false;
    if (!attr_set) {
        cudaFuncSetAttribute(hh_hybrid_r16_kernel,
                             cudaFuncAttributeMaxDynamicSharedMemorySize,
                             ROW_BYTES);
        attr_set = true;
    }

    hh_hybrid_r16_kernel<<<B, THREADS, ROW_BYTES>>>(v, z, out);
}

// round 17
// speedup vs baseline: 1.0005x; 1.0005x over previous
#include <cuda_runtime.h>
#include <cstdint>

// Householder reflection per row, B=8192, L=4096, fp32.
//   out[b,:] = z[b,:] - 2 * v[b,:] * (v.z)/(v.v)
//
// R17 = R16 hybrid dual-path reads (v via TMA bulk -> smem, z via __ldcs
// LDG -> registers; two independent front-end queues, best ncu 52.8us /
// DRAM 83.5%) + R11 early-start (v TMA split into two 8KB stages so the
// dot begins after the first 8KB lands, overlapping the second half and
// the z LDG stream).

constexpr int THREADS = 256;
constexpr int L       = 4096;
constexpr int L4      = L / 4;             // 1024 float4 per row
constexpr int PER     = L4 / THREADS;      // 4 float4 per thread per tensor
constexpr int HALF    = PER / 2;           // 2 per half
constexpr int H4      = L4 / 2;            // 512 float4 per half-row
constexpr int ROW_BYTES  = L * 4;          // 16384 (v in smem)
constexpr int HALF_BYTES = ROW_BYTES / 2;  // 8192

__device__ __forceinline__ uint32_t smem_u32(const void* p) {
    return (uint32_t)__cvta_generic_to_shared(p);
}

__device__ __forceinline__ void mbar_wait0(uint32_t mb) {
    uint32_t done;
    asm volatile(
        "{\n\t.reg .pred p;\n\t"
        "mbarrier.try_wait.parity.acquire.cta.shared::cta.b64 p, [%1], %2;\n\t"
        "selp.b32 %0, 1, 0, p;\n\t}"
        : "=r"(done) : "r"(mb), "r"(0) : "memory");
    while (!done) {
        asm volatile(
            "{\n\t.reg .pred p;\n\t"
            "mbarrier.try_wait.parity.acquire.cta.shared::cta.b64 p, [%1], %2, 0x989680;\n\t"
            "selp.b32 %0, 1, 0, p;\n\t}"
            : "=r"(done) : "r"(mb), "r"(0) : "memory");
    }
}

__global__ __launch_bounds__(THREADS)
void hh_hybrid_r17_kernel(const float4* __restrict__ v,
                          const float4* __restrict__ z,
                          float4* __restrict__ out)
{
    extern __shared__ float4 sm[];            // v: [0,1024)
    __shared__ __align__(8) unsigned long long mbar0;
    __shared__ __align__(8) unsigned long long mbar1;
    __shared__ float s_part[16];              // 8 warps x {vz, vv}
    __shared__ float s_scale;

    const int t    = threadIdx.x;
    const int lane = t & 31;
    const int wid  = t >> 5;
    const size_t base = (size_t)blockIdx.x * L4;

    const uint32_t mb0 = smem_u32(&mbar0);
    const uint32_t mb1 = smem_u32(&mbar1);

    if (t == 0) {
        asm volatile("mbarrier.init.shared::cta.b64 [%0], %1;" :: "r"(mb0), "r"(1));
        asm volatile("mbarrier.init.shared::cta.b64 [%0], %1;" :: "r"(mb1), "r"(1));
        asm volatile("fence.proxy.async.shared::cta;" ::: "memory");
    }
    __syncthreads();

    // TMA path: v in two 8KB stages
    if (t == 0) {
        asm volatile("mbarrier.arrive.expect_tx.shared::cta.b64 _, [%0], %1;"
                     :: "r"(mb0), "r"(HALF_BYTES) : "memory");
        asm volatile("cp.async.bulk.shared::cta.global.mbarrier::complete_tx::bytes"
                     " [%0], [%1], %2, [%3];"
                     :: "r"(smem_u32(sm)), "l"(v + base),
                        "r"(HALF_BYTES), "r"(mb0) : "memory");
        asm volatile("mbarrier.arrive.expect_tx.shared::cta.b64 _, [%0], %1;"
                     :: "r"(mb1), "r"(HALF_BYTES) : "memory");
        asm volatile("cp.async.bulk.shared::cta.global.mbarrier::complete_tx::bytes"
                     " [%0], [%1], %2, [%3];"
                     :: "r"(smem_u32(sm + H4)), "l"(v + base + H4),
                        "r"(HALF_BYTES), "r"(mb1) : "memory");
    }

    // LSU path: z -> registers (streams concurrently with both TMA stages)
    const float4* zg = z + base;
    float4 rz[PER];
    #pragma unroll
    for (int i = 0; i < PER; i++)
        rz[i] = __ldcs(zg + t + i * THREADS);

    float dvz = 0.0f, dvv = 0.0f;

    // ---- v half 0 ----
    mbar_wait0(mb0);
    #pragma unroll
    for (int i = 0; i < HALF; i++) {
        const float4 a = sm[t + i * THREADS];
        dvz += a.x * rz[i].x + a.y * rz[i].y + a.z * rz[i].z + a.w * rz[i].w;
        dvv += a.x * a.x + a.y * a.y + a.z * a.z + a.w * a.w;
    }

    // ---- v half 1 ----
    mbar_wait0(mb1);
    #pragma unroll
    for (int i = HALF; i < PER; i++) {
        const float4 a = sm[H4 + t + (i - HALF) * THREADS];
        dvz += a.x * rz[i].x + a.y * rz[i].y + a.z * rz[i].z + a.w * rz[i].w;
        dvv += a.x * a.x + a.y * a.y + a.z * a.z + a.w * a.w;
    }

    #pragma unroll
    for (int off = 16; off > 0; off >>= 1) {
        dvz += __shfl_xor_sync(0xFFFFFFFFu, dvz, off);
        dvv += __shfl_xor_sync(0xFFFFFFFFu, dvv, off);
    }
    if (lane == 0) { s_part[wid] = dvz; s_part[8 + wid] = dvv; }
    __syncthreads();

    if (wid == 0) {
        float a = (lane < 8) ? s_part[lane] : 0.0f;
        float c = (lane < 8) ? s_part[8 + lane] : 0.0f;
        #pragma unroll
        for (int off = 4; off > 0; off >>= 1) {
            a += __shfl_xor_sync(0xFFFFFFFFu, a, off);
            c += __shfl_xor_sync(0xFFFFFFFFu, c, off);
        }
        if (lane == 0) s_scale = 2.0f * a / c;
    }
    __syncthreads();

    const float nscale = -s_scale;
    float4* og = out + base;

    // Output: v re-read from smem, z from registers, streaming stores
    #pragma unroll
    for (int i = 0; i < HALF; i++) {
        const float4 a = sm[t + i * THREADS];
        float4 o;
        o.x = fmaf(nscale, a.x, rz[i].x);
        o.y = fmaf(nscale, a.y, rz[i].y);
        o.z = fmaf(nscale, a.z, rz[i].z);
        o.w = fmaf(nscale, a.w, rz[i].w);
        __stcs(og + t + i * THREADS, o);
    }
    #pragma unroll
    for (int i = HALF; i < PER; i++) {
        const float4 a = sm[H4 + t + (i - HALF) * THREADS];
        float4 o;
        o.x = fmaf(nscale, a.x, rz[i].x);
        o.y = fmaf(nscale, a.y, rz[i].y);
        o.z = fmaf(nscale, a.z, rz[i].z);
        o.w = fmaf(nscale, a.w, rz[i].w);
        __stcs(og + H4 + t + (i - HALF) * THREADS, o);
    }
}

extern "C" void kernel_launch(void* const* d_in, const int* in_sizes, int n_in,
                              void* d_out, int out_size)
{
    const float4* v = (const float4*)d_in[0];
    const float4* z = (const float4*)d_in[1];
    float4* out = (float4*)d_out;

    const int B = in_sizes[0] / L;    // 8192

    static bool attr_set = false;
    if (!attr_set) {
        cudaFuncSetAttribute(hh_hybrid_r17_kernel,
                             cudaFuncAttributeMaxDynamicSharedMemorySize,
                             ROW_BYTES);
        attr_set = true;
    }

    hh_hybrid_r17_kernel<<<B, THREADS, ROW_BYTES>>>(v, z, out);
}